// round 13
// baseline (speedup 1.0000x reference)
#include <cuda_runtime.h>

// GCN link predictor: 2x GCNConv + edge dot decode.
// R7-proven 3xTF32 tensor GEMM tiles + FEATURE-COLUMN pipelining:
// gemm(colsA) -> agg(colsA) overlaps gemm(colsB), both layers.
// (Aggregation is column-separable: t1[d][c] depends only on hs1[*][c].)

#define NMAX    50000
#define CAP     96
#define PROBE_N 2048

static __device__ __align__(128) int   g_cnt[NMAX];
static __device__ __align__(128) float g_dinv[NMAX];
static __device__ __align__(128) int   g_bucket[(long)NMAX * CAP];
static __device__ __align__(128) float g_hs1[(long)NMAX * 128];  // x@W1 (raw)
static __device__ __align__(128) float g_t1 [(long)NMAX * 128];  // relu layer-1 out
static __device__ __align__(128) float g_hs2[(long)NMAX * 64];   // t1@W2 (raw)
static __device__ __align__(128) float g_z  [(long)NMAX * 64];
static __device__ int g_is64_ei;
static __device__ int g_is64_eli;

// Stream/event handles, once at static init (proven-safe subset).
static cudaStream_t g_s2;
static cudaEvent_t  g_evFork, g_evJoin, g_evG1A, g_evA1A, g_evG2A, g_evA2A;
namespace {
struct HandleInit {
    HandleInit() {
        cudaStreamCreateWithFlags(&g_s2, cudaStreamNonBlocking);
        cudaEventCreateWithFlags(&g_evFork, cudaEventDisableTiming);
        cudaEventCreateWithFlags(&g_evJoin, cudaEventDisableTiming);
        cudaEventCreateWithFlags(&g_evG1A, cudaEventDisableTiming);
        cudaEventCreateWithFlags(&g_evA1A, cudaEventDisableTiming);
        cudaEventCreateWithFlags(&g_evG2A, cudaEventDisableTiming);
        cudaEventCreateWithFlags(&g_evA2A, cudaEventDisableTiming);
    }
} g_hinit;
}

// ---------------------------------------------------------------- init+probe
__global__ void k_init(const unsigned* __restrict__ ei, long ewords,
                       const unsigned* __restrict__ eli, long lwords, int n) {
    int i = blockIdx.x * blockDim.x + threadIdx.x;
    if (i < n) g_cnt[i] = 0;
    if (blockIdx.x == 0) {
        if (threadIdx.x == 0) { g_is64_ei = 1; g_is64_eli = 1; }
        __syncthreads();
        for (int t = threadIdx.x; t < PROBE_N; t += blockDim.x) {
            long idx = 2L * t + 1;
            if (idx < ewords && ei[idx]  != 0u) g_is64_ei  = 0;
            if (idx < lwords && eli[idx] != 0u) g_is64_eli = 0;
        }
    }
}

__device__ __forceinline__ int edge_val(const unsigned* w, long i, int is64) {
    return (int)w[is64 ? (2 * i) : i];
}

__device__ __forceinline__ void build_push(int s, int d, int n) {
    if ((unsigned)s >= (unsigned)n || (unsigned)d >= (unsigned)n) return;
    int pos = atomicAdd(&g_cnt[d], 1);
    if (pos < CAP) g_bucket[(long)d * CAP + pos] = s;
}

__global__ void k_build(const unsigned* __restrict__ ei, int E, int n) {
    int t  = blockIdx.x * blockDim.x + threadIdx.x;
    int e0 = 2 * t;
    if (e0 >= E) return;
    const int  is64 = g_is64_ei;
    const bool has1 = (e0 + 1 < E);

    int s0, s1 = 0, d0, d1 = 0;
    if (is64 && !(E & 1)) {
        const uint4* p = (const uint4*)ei;
        uint4 sv = p[t];
        uint4 dv = p[E / 2 + t];
        s0 = (int)sv.x; s1 = (int)sv.z;
        d0 = (int)dv.x; d1 = (int)dv.z;
    } else if (!is64 && !(E & 1)) {
        const uint2* p = (const uint2*)ei;
        uint2 sv = p[t];
        uint2 dv = p[E / 2 + t];
        s0 = (int)sv.x; s1 = (int)sv.y;
        d0 = (int)dv.x; d1 = (int)dv.y;
    } else {
        s0 = edge_val(ei, e0, is64);
        d0 = edge_val(ei, (long)E + e0, is64);
        if (has1) {
            s1 = edge_val(ei, e0 + 1, is64);
            d1 = edge_val(ei, (long)E + e0 + 1, is64);
        }
    }
    build_push(s0, d0, n);
    if (has1) build_push(s1, d1, n);
}

__global__ void k_dinv(int n) {
    int i = blockIdx.x * blockDim.x + threadIdx.x;
    if (i < n) g_dinv[i] = rsqrtf((float)g_cnt[i] + 1.0f);
}

// ---------------------------------------------------------------- tensor GEMM
__device__ __forceinline__ void split_tf32(float x, unsigned& hi, unsigned& lo) {
    asm("cvt.rna.tf32.f32 %0, %1;" : "=r"(hi) : "f"(x));
    float r = x - __uint_as_float(hi);
    asm("cvt.rna.tf32.f32 %0, %1;" : "=r"(lo) : "f"(r));
}

__device__ __forceinline__ void mma_tf32(float c[4],
                                         unsigned a0, unsigned a1,
                                         unsigned a2, unsigned a3,
                                         unsigned b0, unsigned b1) {
    asm volatile(
        "mma.sync.aligned.m16n8k8.row.col.f32.tf32.tf32.f32 "
        "{%0,%1,%2,%3}, {%4,%5,%6,%7}, {%8,%9}, {%0,%1,%2,%3};\n"
        : "+f"(c[0]), "+f"(c[1]), "+f"(c[2]), "+f"(c[3])
        : "r"(a0), "r"(a1), "r"(a2), "r"(a3), "r"(b0), "r"(b1));
}

// C[:, col_base..col_base+CT) = A[n x 128] @ W[:, cols] (raw).
// 128 rows x CT cols per block, 8 warps, K in two 64-deep phases.
// W staged hi/lo at row stride CT+8 ((CT+8) mod 32 = 8 -> bank-bijective).
template <int NCOLS, int CT>
__global__ void k_gemm_tc(const float* __restrict__ Aext,
                          const float* __restrict__ W,
                          int col_base, int n) {
    constexpr int WST = CT + 8;
    constexpr int NF  = CT / 8;
    __shared__ float Whi[64][WST];
    __shared__ float Wlo[64][WST];

    const float* __restrict__ A = (NCOLS == 128) ? Aext : (const float*)g_t1;
    float* __restrict__ outp    = (NCOLS == 128) ? (float*)g_hs1 : (float*)g_hs2;

    const int tid  = threadIdx.x;
    const int lane = tid & 31;
    const int wid  = tid >> 5;
    const int gID  = lane >> 2;
    const int tg   = lane & 3;

    const int m0 = blockIdx.x * 128 + wid * 16;
    const int r0 = m0 + gID;
    const int r1 = r0 + 8;
    const bool v0 = r0 < n, v1 = r1 < n;
    const float* A0 = A + (size_t)(v0 ? r0 : 0) * 128;
    const float* A1 = A + (size_t)(v1 ? r1 : 0) * 128;

    float acc[NF][4];
#pragma unroll
    for (int i = 0; i < NF; i++)
#pragma unroll
        for (int j = 0; j < 4; j++) acc[i][j] = 0.f;

#pragma unroll
    for (int phase = 0; phase < 2; phase++) {
        const int kbase = phase * 64;
        if (phase) __syncthreads();

#pragma unroll 4
        for (int idx = tid; idx < 64 * CT; idx += 256) {
            int nc = idx & (CT - 1);
            int k  = idx / CT;
            float w = W[(long)(kbase + k) * NCOLS + col_base + nc];
            unsigned hi, lo;
            split_tf32(w, hi, lo);
            Whi[k][nc] = __uint_as_float(hi);
            Wlo[k][nc] = __uint_as_float(lo);
        }
        __syncthreads();

#pragma unroll
        for (int ks = 0; ks < 8; ks++) {
            const int k0 = ks * 8;
            float f0 = A0[kbase + k0 + tg];
            float f1 = A1[kbase + k0 + tg];
            float f2 = A0[kbase + k0 + tg + 4];
            float f3 = A1[kbase + k0 + tg + 4];
            unsigned ah0, al0, ah1, al1, ah2, al2, ah3, al3;
            split_tf32(f0, ah0, al0);
            split_tf32(f1, ah1, al1);
            split_tf32(f2, ah2, al2);
            split_tf32(f3, ah3, al3);

#pragma unroll
            for (int nf = 0; nf < NF; nf++) {
                const int nc = nf * 8 + gID;
                unsigned bh0 = __float_as_uint(Whi[k0 + tg][nc]);
                unsigned bh1 = __float_as_uint(Whi[k0 + tg + 4][nc]);
                unsigned bl0 = __float_as_uint(Wlo[k0 + tg][nc]);
                unsigned bl1 = __float_as_uint(Wlo[k0 + tg + 4][nc]);
                mma_tf32(acc[nf], ah0, ah1, ah2, ah3, bh0, bh1);  // hi*hi
                mma_tf32(acc[nf], ah0, ah1, ah2, ah3, bl0, bl1);  // hi*lo
                mma_tf32(acc[nf], al0, al1, al2, al3, bh0, bh1);  // lo*hi
            }
        }
    }

#pragma unroll
    for (int nf = 0; nf < NF; nf++) {
        int c = col_base + nf * 8 + 2 * tg;
        if (v0) *(float2*)&outp[(long)r0 * NCOLS + c] =
            make_float2(acc[nf][0], acc[nf][1]);
        if (v1) *(float2*)&outp[(long)r1 * NCOLS + c] =
            make_float2(acc[nf][2], acc[nf][3]);
    }
}

// ---------------------------------------------------------------- aggregation
// Column-half of layer 1: t1[d][c] = relu(dinv[d]*(sum dinv[s]*hs1[s][c]
// + dinv[d]*hs1[d][c]) + b1[c]) for c in [colbase, colbase+64).
// Warp per node, lane = one float2 of the 64-col half (256B/gather).
__global__ void k_agg1h(const float* __restrict__ b1, int colbase, int n) {
    int w    = (blockIdx.x * blockDim.x + threadIdx.x) >> 5;
    int lane = threadIdx.x & 31;
    if (w >= n) return;
    const int d  = w;
    const int cc = min(g_cnt[d], CAP);
    const float2* hs = (const float2*)g_hs1;   // row stride 64 float2
    const int  co   = colbase / 2 + lane;
    const long base = (long)d * CAP;

    float2 acc = make_float2(0.f, 0.f);
    int k0 = 0;
    for (; k0 + 32 <= cc; k0 += 32) {
        int   sl = g_bucket[base + k0 + lane];
        float dl = g_dinv[sl];
#pragma unroll
        for (int i = 0; i < 32; i++) {
            int   s  = __shfl_sync(0xffffffffu, sl, i);
            float ws = __shfl_sync(0xffffffffu, dl, i);
            float2 v = hs[(long)s * 64 + co];
            acc.x += ws * v.x; acc.y += ws * v.y;
        }
    }
    if (k0 < cc) {
        int   sl = (k0 + lane < cc) ? g_bucket[base + k0 + lane] : 0;
        float dl = g_dinv[sl];
        int rem = cc - k0;
        for (int i = 0; i < rem; i++) {
            int   s  = __shfl_sync(0xffffffffu, sl, i);
            float ws = __shfl_sync(0xffffffffu, dl, i);
            float2 v = hs[(long)s * 64 + co];
            acc.x += ws * v.x; acc.y += ws * v.y;
        }
    }
    float  di   = g_dinv[d];
    float2 self = hs[(long)d * 64 + co];
    acc.x += di * self.x; acc.y += di * self.y;
    float2 bb = ((const float2*)b1)[co];
    float2 o;
    o.x = fmaxf(di * acc.x + bb.x, 0.f);
    o.y = fmaxf(di * acc.y + bb.y, 0.f);
    ((float2*)g_t1)[(long)d * 64 + co] = o;
}

// Column-half of layer 2 (cols [colbase, colbase+32)).
// Warp per node, lane = one float (128B/gather).
__global__ void k_agg2h(const float* __restrict__ b2, int colbase, int n) {
    int w    = (blockIdx.x * blockDim.x + threadIdx.x) >> 5;
    int lane = threadIdx.x & 31;
    if (w >= n) return;
    const int d  = w;
    const int cc = min(g_cnt[d], CAP);
    const float* hs = (const float*)g_hs2;     // row stride 64 floats
    const int  co   = colbase + lane;
    const long base = (long)d * CAP;

    float acc = 0.f;
    int k0 = 0;
    for (; k0 + 32 <= cc; k0 += 32) {
        int   sl = g_bucket[base + k0 + lane];
        float dl = g_dinv[sl];
#pragma unroll
        for (int i = 0; i < 32; i++) {
            int   s  = __shfl_sync(0xffffffffu, sl, i);
            float ws = __shfl_sync(0xffffffffu, dl, i);
            acc += ws * hs[(long)s * 64 + co];
        }
    }
    if (k0 < cc) {
        int   sl = (k0 + lane < cc) ? g_bucket[base + k0 + lane] : 0;
        float dl = g_dinv[sl];
        int rem = cc - k0;
        for (int i = 0; i < rem; i++) {
            int   s  = __shfl_sync(0xffffffffu, sl, i);
            float ws = __shfl_sync(0xffffffffu, dl, i);
            acc += ws * hs[(long)s * 64 + co];
        }
    }
    float di = g_dinv[d];
    acc += di * hs[(long)d * 64 + co];
    g_z[(long)d * 64 + co] = di * acc + b2[co];
}

// ---------------------------------------------------------------- decode
__global__ void k_decode(const unsigned* __restrict__ eli,
                         float* __restrict__ out, int EL, int n) {
    int gt = blockIdx.x * blockDim.x + threadIdx.x;
    int e  = gt >> 4;
    int j  = gt & 15;
    bool valid = (e < EL);
    int ec = valid ? e : (EL - 1);
    const int is64 = g_is64_eli;
    int u = edge_val(eli, ec, is64);
    int v = edge_val(eli, (long)EL + ec, is64);
    if ((unsigned)u >= (unsigned)n) u = 0;
    if ((unsigned)v >= (unsigned)n) v = 0;
    const float4* z4 = (const float4*)g_z;
    float4 a = z4[(long)u * 16 + j];
    float4 b = z4[(long)v * 16 + j];
    float p = a.x * b.x + a.y * b.y + a.z * b.z + a.w * b.w;
    p += __shfl_xor_sync(0xffffffffu, p, 8, 16);
    p += __shfl_xor_sync(0xffffffffu, p, 4, 16);
    p += __shfl_xor_sync(0xffffffffu, p, 2, 16);
    p += __shfl_xor_sync(0xffffffffu, p, 1, 16);
    if (valid && j == 0) out[e] = p;
}

// ---------------------------------------------------------------- launch
extern "C" void kernel_launch(void* const* d_in, const int* in_sizes, int n_in,
                              void* d_out, int out_size) {
    const float*    x   = (const float*)d_in[0];
    const unsigned* ei  = (const unsigned*)d_in[1];
    const unsigned* eli = (const unsigned*)d_in[2];
    const float*    W1  = (const float*)d_in[3];
    const float*    b1  = (const float*)d_in[4];
    const float*    W2  = (const float*)d_in[5];
    const float*    b2  = (const float*)d_in[6];
    float* out = (float*)d_out;

    const int n  = in_sizes[0] / 128;
    const int E  = in_sizes[1] / 2;
    const int EL = in_sizes[2] / 2;
    const int gemmGrid = (n + 127) / 128;
    const int aggGrid  = (n * 32 + 255) / 256;

    // Side stream: graph build chain (hidden under gemm1).
    cudaEventRecord(g_evFork, 0);
    cudaStreamWaitEvent(g_s2, g_evFork, 0);
    k_init<<<(n + 255) / 256, 256, 0, g_s2>>>(ei, (long)in_sizes[1],
                                              eli, (long)in_sizes[2], n);
    k_build<<<(E / 2 + 255) / 256, 256, 0, g_s2>>>(ei, E, n);
    k_dinv<<<(n + 255) / 256, 256, 0, g_s2>>>(n);
    cudaEventRecord(g_evJoin, g_s2);

    // Layer 1, column-pipelined: g1A -> agg1A (s2)  ||  g1B -> agg1B (main).
    k_gemm_tc<128, 64><<<gemmGrid, 256>>>(x, W1, 0, n);
    cudaEventRecord(g_evG1A, 0);
    k_gemm_tc<128, 64><<<gemmGrid, 256>>>(x, W1, 64, n);

    cudaStreamWaitEvent(g_s2, g_evG1A, 0);             // s2 has build done
    k_agg1h<<<aggGrid, 256, 0, g_s2>>>(b1, 0, n);
    cudaEventRecord(g_evA1A, g_s2);

    cudaStreamWaitEvent(0, g_evJoin, 0);               // main needs graph
    k_agg1h<<<aggGrid, 256>>>(b1, 64, n);

    // Layer 2 (needs full t1): g2A -> agg2A (s2)  ||  g2B -> agg2B (main).
    cudaStreamWaitEvent(0, g_evA1A, 0);
    k_gemm_tc<64, 32><<<gemmGrid, 256>>>(nullptr, W2, 0, n);
    cudaEventRecord(g_evG2A, 0);
    k_gemm_tc<64, 32><<<gemmGrid, 256>>>(nullptr, W2, 32, n);

    cudaStreamWaitEvent(g_s2, g_evG2A, 0);
    k_agg2h<<<aggGrid, 256, 0, g_s2>>>(b2, 0, n);
    cudaEventRecord(g_evA2A, g_s2);

    k_agg2h<<<aggGrid, 256>>>(b2, 32, n);

    // Decode (needs full z).
    cudaStreamWaitEvent(0, g_evA2A, 0);
    k_decode<<<((long)EL * 16 + 255) / 256, 256>>>(eli, out, EL, n);
}

// round 14
// speedup vs baseline: 1.0670x; 1.0670x over previous
#include <cuda_runtime.h>

// GCN link predictor: 2x GCNConv + edge dot decode.
// R12-proven gemm1 + NEW fused agg1+gemm2 kernel (t1 stays in smem; W2
// pre-split to tf32 hi/lo globals, L1-resident). Serial chain is only
// g1 -> fused -> agg2 -> decode; build chain + W2 split hidden on stream 2.

#define NMAX    50000
#define CAP     96
#define PROBE_N 2048
#define WSTRIDE 72   // 64 cols + 8 pad; (72k+nc) mod 32 bijective over warp lanes

static __device__ __align__(128) int   g_cnt[NMAX];
static __device__ __align__(128) float g_dinv[NMAX];
static __device__ __align__(128) int   g_bucket[(long)NMAX * CAP];
static __device__ __align__(128) float g_hs1[(long)NMAX * 128];  // x@W1 (raw)
static __device__ __align__(128) float g_hs2[(long)NMAX * 64];   // t1@W2 (raw)
static __device__ __align__(128) float g_z  [(long)NMAX * 64];
static __device__ __align__(128) float g_W2hi[128 * 64];         // tf32 hi of W2
static __device__ __align__(128) float g_W2lo[128 * 64];         // tf32 lo of W2
static __device__ int g_is64_ei;
static __device__ int g_is64_eli;

// Stream/event handles, once at static init (proven-safe subset).
static cudaStream_t g_s2;
static cudaEvent_t  g_evFork, g_evJoin;
namespace {
struct HandleInit {
    HandleInit() {
        cudaStreamCreateWithFlags(&g_s2, cudaStreamNonBlocking);
        cudaEventCreateWithFlags(&g_evFork, cudaEventDisableTiming);
        cudaEventCreateWithFlags(&g_evJoin, cudaEventDisableTiming);
    }
} g_hinit;
}

// ---------------------------------------------------------------- init+probe
__global__ void k_init(const unsigned* __restrict__ ei, long ewords,
                       const unsigned* __restrict__ eli, long lwords, int n) {
    int i = blockIdx.x * blockDim.x + threadIdx.x;
    if (i < n) g_cnt[i] = 0;
    if (blockIdx.x == 0) {
        if (threadIdx.x == 0) { g_is64_ei = 1; g_is64_eli = 1; }
        __syncthreads();
        for (int t = threadIdx.x; t < PROBE_N; t += blockDim.x) {
            long idx = 2L * t + 1;
            if (idx < ewords && ei[idx]  != 0u) g_is64_ei  = 0;
            if (idx < lwords && eli[idx] != 0u) g_is64_eli = 0;
        }
    }
}

__device__ __forceinline__ int edge_val(const unsigned* w, long i, int is64) {
    return (int)w[is64 ? (2 * i) : i];
}

__device__ __forceinline__ void build_push(int s, int d, int n) {
    if ((unsigned)s >= (unsigned)n || (unsigned)d >= (unsigned)n) return;
    int pos = atomicAdd(&g_cnt[d], 1);
    if (pos < CAP) g_bucket[(long)d * CAP + pos] = s;
}

__global__ void k_build(const unsigned* __restrict__ ei, int E, int n) {
    int t  = blockIdx.x * blockDim.x + threadIdx.x;
    int e0 = 2 * t;
    if (e0 >= E) return;
    const int  is64 = g_is64_ei;
    const bool has1 = (e0 + 1 < E);

    int s0, s1 = 0, d0, d1 = 0;
    if (is64 && !(E & 1)) {
        const uint4* p = (const uint4*)ei;
        uint4 sv = p[t];
        uint4 dv = p[E / 2 + t];
        s0 = (int)sv.x; s1 = (int)sv.z;
        d0 = (int)dv.x; d1 = (int)dv.z;
    } else if (!is64 && !(E & 1)) {
        const uint2* p = (const uint2*)ei;
        uint2 sv = p[t];
        uint2 dv = p[E / 2 + t];
        s0 = (int)sv.x; s1 = (int)sv.y;
        d0 = (int)dv.x; d1 = (int)dv.y;
    } else {
        s0 = edge_val(ei, e0, is64);
        d0 = edge_val(ei, (long)E + e0, is64);
        if (has1) {
            s1 = edge_val(ei, e0 + 1, is64);
            d1 = edge_val(ei, (long)E + e0 + 1, is64);
        }
    }
    build_push(s0, d0, n);
    if (has1) build_push(s1, d1, n);
}

__global__ void k_dinv(int n) {
    int i = blockIdx.x * blockDim.x + threadIdx.x;
    if (i < n) g_dinv[i] = rsqrtf((float)g_cnt[i] + 1.0f);
}

// ---------------------------------------------------------------- helpers
__device__ __forceinline__ void split_tf32(float x, unsigned& hi, unsigned& lo) {
    asm("cvt.rna.tf32.f32 %0, %1;" : "=r"(hi) : "f"(x));
    float r = x - __uint_as_float(hi);
    asm("cvt.rna.tf32.f32 %0, %1;" : "=r"(lo) : "f"(r));
}

__device__ __forceinline__ void mma_tf32(float c[4],
                                         unsigned a0, unsigned a1,
                                         unsigned a2, unsigned a3,
                                         unsigned b0, unsigned b1) {
    asm volatile(
        "mma.sync.aligned.m16n8k8.row.col.f32.tf32.tf32.f32 "
        "{%0,%1,%2,%3}, {%4,%5,%6,%7}, {%8,%9}, {%0,%1,%2,%3};\n"
        : "+f"(c[0]), "+f"(c[1]), "+f"(c[2]), "+f"(c[3])
        : "r"(a0), "r"(a1), "r"(a2), "r"(a3), "r"(b0), "r"(b1));
}

// Pre-split W2 (128x64) into tf32 hi/lo globals (hidden on side stream).
__global__ void k_splitW2(const float* __restrict__ W2) {
    int i = blockIdx.x * blockDim.x + threadIdx.x;
    if (i < 128 * 64) {
        unsigned hi, lo;
        split_tf32(W2[i], hi, lo);
        g_W2hi[i] = __uint_as_float(hi);
        g_W2lo[i] = __uint_as_float(lo);
    }
}

// ---------------------------------------------------------------- gemm1
// g_hs1 = x @ W1 (raw). R12-proven: 128 rows x 64 cols, 8 warps, 2x64-k
// phases, direct A loads, stride-72 Whi/Wlo smem, no reg cap.
__global__ void k_gemm1(const float* __restrict__ A,
                        const float* __restrict__ W, int n) {
    __shared__ float Whi[64][WSTRIDE];
    __shared__ float Wlo[64][WSTRIDE];

    const int tid  = threadIdx.x;
    const int lane = tid & 31;
    const int wid  = tid >> 5;
    const int gID  = lane >> 2;
    const int tg   = lane & 3;
    const int col0 = blockIdx.y * 64;

    const int m0 = blockIdx.x * 128 + wid * 16;
    const int r0 = m0 + gID;
    const int r1 = r0 + 8;
    const bool v0 = r0 < n, v1 = r1 < n;
    const float* A0 = A + (size_t)(v0 ? r0 : 0) * 128;
    const float* A1 = A + (size_t)(v1 ? r1 : 0) * 128;

    float acc[8][4];
#pragma unroll
    for (int i = 0; i < 8; i++)
#pragma unroll
        for (int j = 0; j < 4; j++) acc[i][j] = 0.f;

#pragma unroll
    for (int phase = 0; phase < 2; phase++) {
        const int kbase = phase * 64;
        if (phase) __syncthreads();

#pragma unroll 4
        for (int idx = tid; idx < 64 * 64; idx += 256) {
            int nc = idx & 63;
            int k  = idx >> 6;
            float w = W[(long)(kbase + k) * 128 + col0 + nc];
            unsigned hi, lo;
            split_tf32(w, hi, lo);
            Whi[k][nc] = __uint_as_float(hi);
            Wlo[k][nc] = __uint_as_float(lo);
        }
        __syncthreads();

#pragma unroll
        for (int ks = 0; ks < 8; ks++) {
            const int k0 = ks * 8;
            float f0 = A0[kbase + k0 + tg];
            float f1 = A1[kbase + k0 + tg];
            float f2 = A0[kbase + k0 + tg + 4];
            float f3 = A1[kbase + k0 + tg + 4];
            unsigned ah0, al0, ah1, al1, ah2, al2, ah3, al3;
            split_tf32(f0, ah0, al0);
            split_tf32(f1, ah1, al1);
            split_tf32(f2, ah2, al2);
            split_tf32(f3, ah3, al3);

#pragma unroll
            for (int nf = 0; nf < 8; nf++) {
                const int nc = nf * 8 + gID;
                unsigned bh0 = __float_as_uint(Whi[k0 + tg][nc]);
                unsigned bh1 = __float_as_uint(Whi[k0 + tg + 4][nc]);
                unsigned bl0 = __float_as_uint(Wlo[k0 + tg][nc]);
                unsigned bl1 = __float_as_uint(Wlo[k0 + tg + 4][nc]);
                mma_tf32(acc[nf], ah0, ah1, ah2, ah3, bh0, bh1);  // hi*hi
                mma_tf32(acc[nf], ah0, ah1, ah2, ah3, bl0, bl1);  // hi*lo
                mma_tf32(acc[nf], al0, al1, al2, al3, bh0, bh1);  // lo*hi
            }
        }
    }

#pragma unroll
    for (int nf = 0; nf < 8; nf++) {
        int c = col0 + nf * 8 + 2 * tg;
        if (v0) *(float2*)&g_hs1[(long)r0 * 128 + c] =
            make_float2(acc[nf][0], acc[nf][1]);
        if (v1) *(float2*)&g_hs1[(long)r1 * 128 + c] =
            make_float2(acc[nf][2], acc[nf][3]);
    }
}

// ---------------------------------------------------------------- fused agg1+gemm2
// Phase A (proven agg1): warp w aggregates node d = blk*8 + w:
//   t1 = relu(dinv[d]*(sum dinv[s]*hs1[s] + dinv[d]*hs1[d]) + b1)  -> smem T[w]
// Phase B: 8 warps compute hs2[blk*8..+8) = T @ W2 via 3xTF32 mma.
//   Warp w = column tile nf = w (cols w*8..+7). A rows 8..15 are zero
//   fragments (a1 = a3 = 0), so only the 8 real rows are produced/stored.
__global__ void __launch_bounds__(256) k_agg1_g2(const float* __restrict__ b1,
                                                 int n) {
    __shared__ float T[8][132];   // bank for reads: (4*gID + tg) -> bijective

    const int tid  = threadIdx.x;
    const int lane = tid & 31;
    const int wid  = tid >> 5;
    const int d    = blockIdx.x * 8 + wid;
    const bool dv  = d < n;
    const int dc   = dv ? d : 0;

    // -------- Phase A: aggregation (proven agg1 inner loop) --------
    const int cc = dv ? min(g_cnt[dc], CAP) : 0;
    const float4* hs = (const float4*)g_hs1;
    const long base = (long)dc * CAP;

    float4 acc = make_float4(0.f, 0.f, 0.f, 0.f);
    int k0 = 0;
    for (; k0 + 32 <= cc; k0 += 32) {
        int   sl = g_bucket[base + k0 + lane];
        float dl = g_dinv[sl];
#pragma unroll
        for (int i = 0; i < 32; i++) {
            int   s  = __shfl_sync(0xffffffffu, sl, i);
            float ws = __shfl_sync(0xffffffffu, dl, i);
            float4 v = hs[(long)s * 32 + lane];
            acc.x += ws * v.x; acc.y += ws * v.y;
            acc.z += ws * v.z; acc.w += ws * v.w;
        }
    }
    if (k0 < cc) {
        int   sl = (k0 + lane < cc) ? g_bucket[base + k0 + lane] : 0;
        float dl = g_dinv[sl];
        int rem = cc - k0;
        for (int i = 0; i < rem; i++) {
            int   s  = __shfl_sync(0xffffffffu, sl, i);
            float ws = __shfl_sync(0xffffffffu, dl, i);
            float4 v = hs[(long)s * 32 + lane];
            acc.x += ws * v.x; acc.y += ws * v.y;
            acc.z += ws * v.z; acc.w += ws * v.w;
        }
    }
    float  di   = dv ? g_dinv[dc] : 0.f;
    float4 self = hs[(long)dc * 32 + lane];
    acc.x += di * self.x; acc.y += di * self.y;
    acc.z += di * self.z; acc.w += di * self.w;
    float4 bb = ((const float4*)b1)[lane];
    float4 o;
    o.x = fmaxf(di * acc.x + bb.x, 0.f);
    o.y = fmaxf(di * acc.y + bb.y, 0.f);
    o.z = fmaxf(di * acc.z + bb.z, 0.f);
    o.w = fmaxf(di * acc.w + bb.w, 0.f);
    *(float4*)&T[wid][4 * lane] = o;
    __syncthreads();

    // -------- Phase B: hs2 tile = T (8x128) @ W2 (128x64), 3xTF32 --------
    const int gID = lane >> 2;
    const int tg  = lane & 3;
    const int nc  = wid * 8 + gID;   // this warp's column + lane's col-in-tile

    float c4[4] = {0.f, 0.f, 0.f, 0.f};
#pragma unroll
    for (int ks = 0; ks < 16; ks++) {
        const int kk = ks * 8;
        float f0 = T[gID][kk + tg];
        float f2 = T[gID][kk + tg + 4];
        unsigned ah0, al0, ah2, al2;
        split_tf32(f0, ah0, al0);
        split_tf32(f2, ah2, al2);

        unsigned bh0 = __float_as_uint(g_W2hi[(kk + tg) * 64 + nc]);
        unsigned bh1 = __float_as_uint(g_W2hi[(kk + tg + 4) * 64 + nc]);
        unsigned bl0 = __float_as_uint(g_W2lo[(kk + tg) * 64 + nc]);
        unsigned bl1 = __float_as_uint(g_W2lo[(kk + tg + 4) * 64 + nc]);

        mma_tf32(c4, ah0, 0u, ah2, 0u, bh0, bh1);  // hi*hi
        mma_tf32(c4, ah0, 0u, ah2, 0u, bl0, bl1);  // hi*lo
        mma_tf32(c4, al0, 0u, al2, 0u, bh0, bh1);  // lo*hi
    }

    // C row gID = node blk*8 + gID, cols wid*8 + 2tg, +1. Rows 8..15 unused.
    int node = blockIdx.x * 8 + gID;
    if (node < n)
        *(float2*)&g_hs2[(long)node * 64 + wid * 8 + 2 * tg] =
            make_float2(c4[0], c4[1]);
}

// ---------------------------------------------------------------- agg2
// z[d] = dinv[d] * (sum dinv[s]*hs2[s] + dinv[d]*hs2[d]) + b2. Half-warp/node.
__global__ void k_agg2(const float* __restrict__ b2, int n) {
    int gt   = blockIdx.x * blockDim.x + threadIdx.x;
    int grp  = gt >> 4;
    int j    = gt & 15;
    int lane = threadIdx.x & 31;
    unsigned gmask = 0xFFFFu << (lane & 16);
    if (grp >= n) return;
    const int d  = grp;
    const int cc = min(g_cnt[d], CAP);
    const float4* hs = (const float4*)g_hs2;
    const long base = (long)d * CAP;

    float4 acc = make_float4(0.f, 0.f, 0.f, 0.f);
    int k0 = 0;
    for (; k0 + 16 <= cc; k0 += 16) {
        int   sl = g_bucket[base + k0 + j];
        float dl = g_dinv[sl];
#pragma unroll
        for (int i = 0; i < 16; i++) {
            int   s  = __shfl_sync(gmask, sl, i, 16);
            float ws = __shfl_sync(gmask, dl, i, 16);
            float4 v = hs[(long)s * 16 + j];
            acc.x += ws * v.x; acc.y += ws * v.y;
            acc.z += ws * v.z; acc.w += ws * v.w;
        }
    }
    if (k0 < cc) {
        int   sl = (k0 + j < cc) ? g_bucket[base + k0 + j] : 0;
        float dl = g_dinv[sl];
        int rem = cc - k0;
        for (int i = 0; i < rem; i++) {
            int   s  = __shfl_sync(gmask, sl, i, 16);
            float ws = __shfl_sync(gmask, dl, i, 16);
            float4 v = hs[(long)s * 16 + j];
            acc.x += ws * v.x; acc.y += ws * v.y;
            acc.z += ws * v.z; acc.w += ws * v.w;
        }
    }
    float  di   = g_dinv[d];
    float4 self = hs[(long)d * 16 + j];
    acc.x += di * self.x; acc.y += di * self.y;
    acc.z += di * self.z; acc.w += di * self.w;
    float4 bb = ((const float4*)b2)[j];
    float4 o;
    o.x = di * acc.x + bb.x;
    o.y = di * acc.y + bb.y;
    o.z = di * acc.z + bb.z;
    o.w = di * acc.w + bb.w;
    ((float4*)g_z)[(long)d * 16 + j] = o;
}

// ---------------------------------------------------------------- decode
__global__ void k_decode(const unsigned* __restrict__ eli,
                         float* __restrict__ out, int EL, int n) {
    int gt = blockIdx.x * blockDim.x + threadIdx.x;
    int e  = gt >> 4;
    int j  = gt & 15;
    bool valid = (e < EL);
    int ec = valid ? e : (EL - 1);
    const int is64 = g_is64_eli;
    int u = edge_val(eli, ec, is64);
    int v = edge_val(eli, (long)EL + ec, is64);
    if ((unsigned)u >= (unsigned)n) u = 0;
    if ((unsigned)v >= (unsigned)n) v = 0;
    const float4* z4 = (const float4*)g_z;
    float4 a = z4[(long)u * 16 + j];
    float4 b = z4[(long)v * 16 + j];
    float p = a.x * b.x + a.y * b.y + a.z * b.z + a.w * b.w;
    p += __shfl_xor_sync(0xffffffffu, p, 8, 16);
    p += __shfl_xor_sync(0xffffffffu, p, 4, 16);
    p += __shfl_xor_sync(0xffffffffu, p, 2, 16);
    p += __shfl_xor_sync(0xffffffffu, p, 1, 16);
    if (valid && j == 0) out[e] = p;
}

// ---------------------------------------------------------------- launch
extern "C" void kernel_launch(void* const* d_in, const int* in_sizes, int n_in,
                              void* d_out, int out_size) {
    const float*    x   = (const float*)d_in[0];
    const unsigned* ei  = (const unsigned*)d_in[1];
    const unsigned* eli = (const unsigned*)d_in[2];
    const float*    W1  = (const float*)d_in[3];
    const float*    b1  = (const float*)d_in[4];
    const float*    W2  = (const float*)d_in[5];
    const float*    b2  = (const float*)d_in[6];
    float* out = (float*)d_out;

    const int n  = in_sizes[0] / 128;
    const int E  = in_sizes[1] / 2;
    const int EL = in_sizes[2] / 2;

    // Side stream: graph build chain + W2 split (hidden under gemm1).
    cudaEventRecord(g_evFork, 0);
    cudaStreamWaitEvent(g_s2, g_evFork, 0);
    k_init<<<(n + 255) / 256, 256, 0, g_s2>>>(ei, (long)in_sizes[1],
                                              eli, (long)in_sizes[2], n);
    k_build<<<(E / 2 + 255) / 256, 256, 0, g_s2>>>(ei, E, n);
    k_dinv<<<(n + 255) / 256, 256, 0, g_s2>>>(n);
    k_splitW2<<<(128 * 64 + 255) / 256, 256, 0, g_s2>>>(W2);
    cudaEventRecord(g_evJoin, g_s2);

    // Main serial chain: gemm1 -> fused(agg1+gemm2) -> agg2 -> decode.
    dim3 g1((n + 127) / 128, 2);
    k_gemm1<<<g1, 256>>>(x, W1, n);

    cudaStreamWaitEvent(0, g_evJoin, 0);
    k_agg1_g2<<<(n + 7) / 8, 256>>>(b1, n);

    k_agg2<<<(n * 16 + 255) / 256, 256>>>(b2, n);

    k_decode<<<((long)EL * 16 + 255) / 256, 256>>>(eli, out, EL, n);
}

// round 15
// speedup vs baseline: 1.2609x; 1.1817x over previous
#include <cuda_runtime.h>

// GCN link predictor: 2x GCNConv + edge dot decode.
// Proven-best combination (R12, 144.8us): R7 GEMM (128x64 tile, 256 thr,
// 2x64-k phases, direct A global loads, stride-72 Whi/Wlo smem) + two-stream
// chunk pipeline (build-chain under gemm1; agg1/gemm2 split into node chunks).

#define NMAX    50000
#define CAP     96
#define PROBE_N 2048
#define WSTRIDE 72   // 64 cols + 8 pad; (72k+nc) mod 32 bijective over warp lanes

static __device__ __align__(128) int   g_cnt[NMAX];
static __device__ __align__(128) float g_dinv[NMAX];
static __device__ __align__(128) int   g_bucket[(long)NMAX * CAP];
static __device__ __align__(128) float g_hs1[(long)NMAX * 128];  // x@W1 (raw)
static __device__ __align__(128) float g_t1 [(long)NMAX * 128];  // relu layer-1 out
static __device__ __align__(128) float g_hs2[(long)NMAX * 64];   // t1@W2 (raw)
static __device__ __align__(128) float g_z  [(long)NMAX * 64];
static __device__ int g_is64_ei;
static __device__ int g_is64_eli;

// Stream/event handles, once at static init (proven-safe subset).
static cudaStream_t g_s2;
static cudaEvent_t  g_evFork, g_evJoin, g_evG1, g_evB;
namespace {
struct HandleInit {
    HandleInit() {
        cudaStreamCreateWithFlags(&g_s2, cudaStreamNonBlocking);
        cudaEventCreateWithFlags(&g_evFork, cudaEventDisableTiming);
        cudaEventCreateWithFlags(&g_evJoin, cudaEventDisableTiming);
        cudaEventCreateWithFlags(&g_evG1,   cudaEventDisableTiming);
        cudaEventCreateWithFlags(&g_evB,    cudaEventDisableTiming);
    }
} g_hinit;
}

// ---------------------------------------------------------------- init+probe
__global__ void k_init(const unsigned* __restrict__ ei, long ewords,
                       const unsigned* __restrict__ eli, long lwords, int n) {
    int i = blockIdx.x * blockDim.x + threadIdx.x;
    if (i < n) g_cnt[i] = 0;
    if (blockIdx.x == 0) {
        if (threadIdx.x == 0) { g_is64_ei = 1; g_is64_eli = 1; }
        __syncthreads();
        for (int t = threadIdx.x; t < PROBE_N; t += blockDim.x) {
            long idx = 2L * t + 1;
            if (idx < ewords && ei[idx]  != 0u) g_is64_ei  = 0;
            if (idx < lwords && eli[idx] != 0u) g_is64_eli = 0;
        }
    }
}

__device__ __forceinline__ int edge_val(const unsigned* w, long i, int is64) {
    return (int)w[is64 ? (2 * i) : i];
}

__device__ __forceinline__ void build_push(int s, int d, int n) {
    if ((unsigned)s >= (unsigned)n || (unsigned)d >= (unsigned)n) return;
    int pos = atomicAdd(&g_cnt[d], 1);
    if (pos < CAP) g_bucket[(long)d * CAP + pos] = s;
}

__global__ void k_build(const unsigned* __restrict__ ei, int E, int n) {
    int t  = blockIdx.x * blockDim.x + threadIdx.x;
    int e0 = 2 * t;
    if (e0 >= E) return;
    const int  is64 = g_is64_ei;
    const bool has1 = (e0 + 1 < E);

    int s0, s1 = 0, d0, d1 = 0;
    if (is64 && !(E & 1)) {
        const uint4* p = (const uint4*)ei;
        uint4 sv = p[t];
        uint4 dv = p[E / 2 + t];
        s0 = (int)sv.x; s1 = (int)sv.z;
        d0 = (int)dv.x; d1 = (int)dv.z;
    } else if (!is64 && !(E & 1)) {
        const uint2* p = (const uint2*)ei;
        uint2 sv = p[t];
        uint2 dv = p[E / 2 + t];
        s0 = (int)sv.x; s1 = (int)sv.y;
        d0 = (int)dv.x; d1 = (int)dv.y;
    } else {
        s0 = edge_val(ei, e0, is64);
        d0 = edge_val(ei, (long)E + e0, is64);
        if (has1) {
            s1 = edge_val(ei, e0 + 1, is64);
            d1 = edge_val(ei, (long)E + e0 + 1, is64);
        }
    }
    build_push(s0, d0, n);
    if (has1) build_push(s1, d1, n);
}

__global__ void k_dinv(int n) {
    int i = blockIdx.x * blockDim.x + threadIdx.x;
    if (i < n) g_dinv[i] = rsqrtf((float)g_cnt[i] + 1.0f);
}

// ---------------------------------------------------------------- tensor GEMM
__device__ __forceinline__ void split_tf32(float x, unsigned& hi, unsigned& lo) {
    asm("cvt.rna.tf32.f32 %0, %1;" : "=r"(hi) : "f"(x));
    float r = x - __uint_as_float(hi);
    asm("cvt.rna.tf32.f32 %0, %1;" : "=r"(lo) : "f"(r));
}

__device__ __forceinline__ void mma_tf32(float c[4],
                                         unsigned a0, unsigned a1,
                                         unsigned a2, unsigned a3,
                                         unsigned b0, unsigned b1) {
    asm volatile(
        "mma.sync.aligned.m16n8k8.row.col.f32.tf32.tf32.f32 "
        "{%0,%1,%2,%3}, {%4,%5,%6,%7}, {%8,%9}, {%0,%1,%2,%3};\n"
        : "+f"(c[0]), "+f"(c[1]), "+f"(c[2]), "+f"(c[3])
        : "r"(a0), "r"(a1), "r"(a2), "r"(a3), "r"(b0), "r"(b1));
}

// C[rows rowbase..rowlim) = A @ W (raw). R7-proven tile: 128 rows x 64 cols,
// 8 warps, K in two 64-deep phases, A read directly from global (L2-hot),
// W staged as separate Whi/Wlo stride-72 (all LDS conflict-free). No reg cap.
template <int NCOLS>
__global__ void k_gemm_tc(const float* __restrict__ Aext,
                          const float* __restrict__ W,
                          int rowbase, int rowlim) {
    __shared__ float Whi[64][WSTRIDE];
    __shared__ float Wlo[64][WSTRIDE];

    const float* __restrict__ A = (NCOLS == 128) ? Aext : (const float*)g_t1;
    float* __restrict__ outp    = (NCOLS == 128) ? (float*)g_hs1 : (float*)g_hs2;

    const int tid  = threadIdx.x;
    const int lane = tid & 31;
    const int wid  = tid >> 5;
    const int gID  = lane >> 2;
    const int tg   = lane & 3;
    const int col0 = blockIdx.y * 64;

    const int m0 = rowbase + blockIdx.x * 128 + wid * 16;
    const int r0 = m0 + gID;
    const int r1 = r0 + 8;
    const bool v0 = r0 < rowlim, v1 = r1 < rowlim;
    const float* A0 = A + (size_t)(v0 ? r0 : 0) * 128;
    const float* A1 = A + (size_t)(v1 ? r1 : 0) * 128;

    float acc[8][4];
#pragma unroll
    for (int i = 0; i < 8; i++)
#pragma unroll
        for (int j = 0; j < 4; j++) acc[i][j] = 0.f;

#pragma unroll
    for (int phase = 0; phase < 2; phase++) {
        const int kbase = phase * 64;
        if (phase) __syncthreads();

#pragma unroll 4
        for (int idx = tid; idx < 64 * 64; idx += 256) {
            int nc = idx & 63;
            int k  = idx >> 6;
            float w = W[(long)(kbase + k) * NCOLS + col0 + nc];
            unsigned hi, lo;
            split_tf32(w, hi, lo);
            Whi[k][nc] = __uint_as_float(hi);
            Wlo[k][nc] = __uint_as_float(lo);
        }
        __syncthreads();

#pragma unroll
        for (int ks = 0; ks < 8; ks++) {
            const int k0 = ks * 8;
            float f0 = A0[kbase + k0 + tg];
            float f1 = A1[kbase + k0 + tg];
            float f2 = A0[kbase + k0 + tg + 4];
            float f3 = A1[kbase + k0 + tg + 4];
            unsigned ah0, al0, ah1, al1, ah2, al2, ah3, al3;
            split_tf32(f0, ah0, al0);
            split_tf32(f1, ah1, al1);
            split_tf32(f2, ah2, al2);
            split_tf32(f3, ah3, al3);

#pragma unroll
            for (int nf = 0; nf < 8; nf++) {
                const int nc = nf * 8 + gID;
                unsigned bh0 = __float_as_uint(Whi[k0 + tg][nc]);
                unsigned bh1 = __float_as_uint(Whi[k0 + tg + 4][nc]);
                unsigned bl0 = __float_as_uint(Wlo[k0 + tg][nc]);
                unsigned bl1 = __float_as_uint(Wlo[k0 + tg + 4][nc]);
                mma_tf32(acc[nf], ah0, ah1, ah2, ah3, bh0, bh1);  // hi*hi
                mma_tf32(acc[nf], ah0, ah1, ah2, ah3, bl0, bl1);  // hi*lo
                mma_tf32(acc[nf], al0, al1, al2, al3, bh0, bh1);  // lo*hi
            }
        }
    }

#pragma unroll
    for (int nf = 0; nf < 8; nf++) {
        int c = col0 + nf * 8 + 2 * tg;
        if (v0) *(float2*)&outp[(long)r0 * NCOLS + c] =
            make_float2(acc[nf][0], acc[nf][1]);
        if (v1) *(float2*)&outp[(long)r1 * NCOLS + c] =
            make_float2(acc[nf][2], acc[nf][3]);
    }
}

// ---------------------------------------------------------------- aggregation
// t1[d] = relu(dinv[d] * (sum_s dinv[s]*h[s] + dinv[d]*h[d]) + b1)
__global__ void k_agg1(const float* __restrict__ b1, int dbase, int dcnt) {
    int w    = (blockIdx.x * blockDim.x + threadIdx.x) >> 5;
    int lane = threadIdx.x & 31;
    if (w >= dcnt) return;
    const int d  = dbase + w;
    const int cc = min(g_cnt[d], CAP);
    const float4* hs = (const float4*)g_hs1;
    const long base = (long)d * CAP;

    float4 acc = make_float4(0.f, 0.f, 0.f, 0.f);
    int k0 = 0;
    for (; k0 + 32 <= cc; k0 += 32) {
        int   sl = g_bucket[base + k0 + lane];
        float dl = g_dinv[sl];
#pragma unroll
        for (int i = 0; i < 32; i++) {
            int   s = __shfl_sync(0xffffffffu, sl, i);
            float ws = __shfl_sync(0xffffffffu, dl, i);
            float4 v = hs[(long)s * 32 + lane];
            acc.x += ws * v.x; acc.y += ws * v.y;
            acc.z += ws * v.z; acc.w += ws * v.w;
        }
    }
    if (k0 < cc) {
        int   sl = (k0 + lane < cc) ? g_bucket[base + k0 + lane] : 0;
        float dl = g_dinv[sl];
        int rem = cc - k0;
        for (int i = 0; i < rem; i++) {
            int   s = __shfl_sync(0xffffffffu, sl, i);
            float ws = __shfl_sync(0xffffffffu, dl, i);
            float4 v = hs[(long)s * 32 + lane];
            acc.x += ws * v.x; acc.y += ws * v.y;
            acc.z += ws * v.z; acc.w += ws * v.w;
        }
    }
    float  di   = g_dinv[d];
    float4 self = hs[(long)d * 32 + lane];
    acc.x += di * self.x; acc.y += di * self.y;
    acc.z += di * self.z; acc.w += di * self.w;
    float4 bb = ((const float4*)b1)[lane];
    float4 o;
    o.x = fmaxf(di * acc.x + bb.x, 0.f);
    o.y = fmaxf(di * acc.y + bb.y, 0.f);
    o.z = fmaxf(di * acc.z + bb.z, 0.f);
    o.w = fmaxf(di * acc.w + bb.w, 0.f);
    ((float4*)g_t1)[(long)d * 32 + lane] = o;
}

__global__ void k_agg2(const float* __restrict__ b2, int n) {
    int gt   = blockIdx.x * blockDim.x + threadIdx.x;
    int grp  = gt >> 4;
    int j    = gt & 15;
    int lane = threadIdx.x & 31;
    unsigned gmask = 0xFFFFu << (lane & 16);
    if (grp >= n) return;
    const int d  = grp;
    const int cc = min(g_cnt[d], CAP);
    const float4* hs = (const float4*)g_hs2;
    const long base = (long)d * CAP;

    float4 acc = make_float4(0.f, 0.f, 0.f, 0.f);
    int k0 = 0;
    for (; k0 + 16 <= cc; k0 += 16) {
        int   sl = g_bucket[base + k0 + j];
        float dl = g_dinv[sl];
#pragma unroll
        for (int i = 0; i < 16; i++) {
            int   s = __shfl_sync(gmask, sl, i, 16);
            float ws = __shfl_sync(gmask, dl, i, 16);
            float4 v = hs[(long)s * 16 + j];
            acc.x += ws * v.x; acc.y += ws * v.y;
            acc.z += ws * v.z; acc.w += ws * v.w;
        }
    }
    if (k0 < cc) {
        int   sl = (k0 + j < cc) ? g_bucket[base + k0 + j] : 0;
        float dl = g_dinv[sl];
        int rem = cc - k0;
        for (int i = 0; i < rem; i++) {
            int   s = __shfl_sync(gmask, sl, i, 16);
            float ws = __shfl_sync(gmask, dl, i, 16);
            float4 v = hs[(long)s * 16 + j];
            acc.x += ws * v.x; acc.y += ws * v.y;
            acc.z += ws * v.z; acc.w += ws * v.w;
        }
    }
    float  di   = g_dinv[d];
    float4 self = hs[(long)d * 16 + j];
    acc.x += di * self.x; acc.y += di * self.y;
    acc.z += di * self.z; acc.w += di * self.w;
    float4 bb = ((const float4*)b2)[j];
    float4 o;
    o.x = di * acc.x + bb.x;
    o.y = di * acc.y + bb.y;
    o.z = di * acc.z + bb.z;
    o.w = di * acc.w + bb.w;
    ((float4*)g_z)[(long)d * 16 + j] = o;
}

// ---------------------------------------------------------------- decode
__global__ void k_decode(const unsigned* __restrict__ eli,
                         float* __restrict__ out, int EL, int n) {
    int gt = blockIdx.x * blockDim.x + threadIdx.x;
    int e  = gt >> 4;
    int j  = gt & 15;
    bool valid = (e < EL);
    int ec = valid ? e : (EL - 1);
    const int is64 = g_is64_eli;
    int u = edge_val(eli, ec, is64);
    int v = edge_val(eli, (long)EL + ec, is64);
    if ((unsigned)u >= (unsigned)n) u = 0;
    if ((unsigned)v >= (unsigned)n) v = 0;
    const float4* z4 = (const float4*)g_z;
    float4 a = z4[(long)u * 16 + j];
    float4 b = z4[(long)v * 16 + j];
    float p = a.x * b.x + a.y * b.y + a.z * b.z + a.w * b.w;
    p += __shfl_xor_sync(0xffffffffu, p, 8, 16);
    p += __shfl_xor_sync(0xffffffffu, p, 4, 16);
    p += __shfl_xor_sync(0xffffffffu, p, 2, 16);
    p += __shfl_xor_sync(0xffffffffu, p, 1, 16);
    if (valid && j == 0) out[e] = p;
}

// ---------------------------------------------------------------- launch
extern "C" void kernel_launch(void* const* d_in, const int* in_sizes, int n_in,
                              void* d_out, int out_size) {
    const float*    x   = (const float*)d_in[0];
    const unsigned* ei  = (const unsigned*)d_in[1];
    const unsigned* eli = (const unsigned*)d_in[2];
    const float*    W1  = (const float*)d_in[3];
    const float*    b1  = (const float*)d_in[4];
    const float*    W2  = (const float*)d_in[5];
    const float*    b2  = (const float*)d_in[6];
    float* out = (float*)d_out;

    const int n  = in_sizes[0] / 128;
    const int E  = in_sizes[1] / 2;
    const int EL = in_sizes[2] / 2;

    // Node chunks: A = [0, nA) multiple of 128, B = [nA, n).
    const int nA = ((n / 2) / 128) * 128;
    const int nB = n - nA;

    // Fork: side stream builds graph structure during the layer-1 GEMM.
    cudaEventRecord(g_evFork, 0);
    cudaStreamWaitEvent(g_s2, g_evFork, 0);

    k_init<<<(n + 255) / 256, 256, 0, g_s2>>>(ei, (long)in_sizes[1],
                                              eli, (long)in_sizes[2], n);
    k_build<<<(E / 2 + 255) / 256, 256, 0, g_s2>>>(ei, E, n);
    k_dinv<<<(n + 255) / 256, 256, 0, g_s2>>>(n);
    cudaEventRecord(g_evJoin, g_s2);

    dim3 g1((n + 127) / 128, 2);
    k_gemm_tc<128><<<g1, 256>>>(x, W1, 0, n);
    cudaEventRecord(g_evG1, 0);

    // Main stream: needs graph (evJoin) before aggregation.
    cudaStreamWaitEvent(0, g_evJoin, 0);
    // Side stream: needs gemm1 (evG1) before its agg1 chunk.
    cudaStreamWaitEvent(g_s2, g_evG1, 0);

    // Pipelined chunks: agg1_A/gemm2_A on stream0 || agg1_B/gemm2_B on s2.
    k_agg1<<<(nA * 32 + 255) / 256, 256>>>(b1, 0, nA);
    k_agg1<<<(nB * 32 + 255) / 256, 256, 0, g_s2>>>(b1, nA, nB);

    dim3 g2a(nA / 128, 1);
    k_gemm_tc<64><<<g2a, 256>>>(nullptr, W2, 0, nA);
    dim3 g2b((nB + 127) / 128, 1);
    k_gemm_tc<64><<<g2b, 256, 0, g_s2>>>(nullptr, W2, nA, n);
    cudaEventRecord(g_evB, g_s2);
    cudaStreamWaitEvent(0, g_evB, 0);

    k_agg2<<<(n * 16 + 255) / 256, 256>>>(b2, n);

    k_decode<<<((long)EL * 16 + 255) / 256, 256>>>(eli, out, EL, n);
}

// round 16
// speedup vs baseline: 1.2693x; 1.0067x over previous
#include <cuda_runtime.h>

// GCN link predictor: 2x GCNConv + edge dot decode.
// R12/R15-proven structure (R7 GEMM tiles + two-stream chunk pipeline)
// + pre-split tf32 hi/lo weights: GEMM staging becomes pure float4 copy
// (8x fewer staging instructions), mainloop byte-identical.

#define NMAX    50000
#define CAP     96
#define PROBE_N 2048
#define WSTRIDE 72   // 64 cols + 8 pad; (72k+nc) mod 32 bijective over warp lanes

static __device__ __align__(128) int   g_cnt[NMAX];
static __device__ __align__(128) float g_dinv[NMAX];
static __device__ __align__(128) int   g_bucket[(long)NMAX * CAP];
static __device__ __align__(128) float g_hs1[(long)NMAX * 128];  // x@W1 (raw)
static __device__ __align__(128) float g_t1 [(long)NMAX * 128];  // relu layer-1 out
static __device__ __align__(128) float g_hs2[(long)NMAX * 64];   // t1@W2 (raw)
static __device__ __align__(128) float g_z  [(long)NMAX * 64];
static __device__ __align__(128) float g_W1hi[128 * 128];
static __device__ __align__(128) float g_W1lo[128 * 128];
static __device__ __align__(128) float g_W2hi[128 * 64];
static __device__ __align__(128) float g_W2lo[128 * 64];
static __device__ int g_is64_ei;
static __device__ int g_is64_eli;

// Stream/event handles, once at static init (proven-safe subset).
static cudaStream_t g_s2;
static cudaEvent_t  g_evFork, g_evJoin, g_evG1, g_evB;
namespace {
struct HandleInit {
    HandleInit() {
        cudaStreamCreateWithFlags(&g_s2, cudaStreamNonBlocking);
        cudaEventCreateWithFlags(&g_evFork, cudaEventDisableTiming);
        cudaEventCreateWithFlags(&g_evJoin, cudaEventDisableTiming);
        cudaEventCreateWithFlags(&g_evG1,   cudaEventDisableTiming);
        cudaEventCreateWithFlags(&g_evB,    cudaEventDisableTiming);
    }
} g_hinit;
}

// ---------------------------------------------------------------- init+probe
__global__ void k_init(const unsigned* __restrict__ ei, long ewords,
                       const unsigned* __restrict__ eli, long lwords, int n) {
    int i = blockIdx.x * blockDim.x + threadIdx.x;
    if (i < n) g_cnt[i] = 0;
    if (blockIdx.x == 0) {
        if (threadIdx.x == 0) { g_is64_ei = 1; g_is64_eli = 1; }
        __syncthreads();
        for (int t = threadIdx.x; t < PROBE_N; t += blockDim.x) {
            long idx = 2L * t + 1;
            if (idx < ewords && ei[idx]  != 0u) g_is64_ei  = 0;
            if (idx < lwords && eli[idx] != 0u) g_is64_eli = 0;
        }
    }
}

__device__ __forceinline__ int edge_val(const unsigned* w, long i, int is64) {
    return (int)w[is64 ? (2 * i) : i];
}

__device__ __forceinline__ void build_push(int s, int d, int n) {
    if ((unsigned)s >= (unsigned)n || (unsigned)d >= (unsigned)n) return;
    int pos = atomicAdd(&g_cnt[d], 1);
    if (pos < CAP) g_bucket[(long)d * CAP + pos] = s;
}

__global__ void k_build(const unsigned* __restrict__ ei, int E, int n) {
    int t  = blockIdx.x * blockDim.x + threadIdx.x;
    int e0 = 2 * t;
    if (e0 >= E) return;
    const int  is64 = g_is64_ei;
    const bool has1 = (e0 + 1 < E);

    int s0, s1 = 0, d0, d1 = 0;
    if (is64 && !(E & 1)) {
        const uint4* p = (const uint4*)ei;
        uint4 sv = p[t];
        uint4 dv = p[E / 2 + t];
        s0 = (int)sv.x; s1 = (int)sv.z;
        d0 = (int)dv.x; d1 = (int)dv.z;
    } else if (!is64 && !(E & 1)) {
        const uint2* p = (const uint2*)ei;
        uint2 sv = p[t];
        uint2 dv = p[E / 2 + t];
        s0 = (int)sv.x; s1 = (int)sv.y;
        d0 = (int)dv.x; d1 = (int)dv.y;
    } else {
        s0 = edge_val(ei, e0, is64);
        d0 = edge_val(ei, (long)E + e0, is64);
        if (has1) {
            s1 = edge_val(ei, e0 + 1, is64);
            d1 = edge_val(ei, (long)E + e0 + 1, is64);
        }
    }
    build_push(s0, d0, n);
    if (has1) build_push(s1, d1, n);
}

__global__ void k_dinv(int n) {
    int i = blockIdx.x * blockDim.x + threadIdx.x;
    if (i < n) g_dinv[i] = rsqrtf((float)g_cnt[i] + 1.0f);
}

// ---------------------------------------------------------------- helpers
__device__ __forceinline__ void split_tf32(float x, unsigned& hi, unsigned& lo) {
    asm("cvt.rna.tf32.f32 %0, %1;" : "=r"(hi) : "f"(x));
    float r = x - __uint_as_float(hi);
    asm("cvt.rna.tf32.f32 %0, %1;" : "=r"(lo) : "f"(r));
}

__device__ __forceinline__ void mma_tf32(float c[4],
                                         unsigned a0, unsigned a1,
                                         unsigned a2, unsigned a3,
                                         unsigned b0, unsigned b1) {
    asm volatile(
        "mma.sync.aligned.m16n8k8.row.col.f32.tf32.tf32.f32 "
        "{%0,%1,%2,%3}, {%4,%5,%6,%7}, {%8,%9}, {%0,%1,%2,%3};\n"
        : "+f"(c[0]), "+f"(c[1]), "+f"(c[2]), "+f"(c[3])
        : "r"(a0), "r"(a1), "r"(a2), "r"(a3), "r"(b0), "r"(b1));
}

// Pre-split both weight matrices into tf32 hi/lo (run once, before gemm1).
__global__ void k_splitW(const float* __restrict__ W1,
                         const float* __restrict__ W2) {
    int i = blockIdx.x * blockDim.x + threadIdx.x;
    unsigned hi, lo;
    if (i < 128 * 128) {
        split_tf32(W1[i], hi, lo);
        g_W1hi[i] = __uint_as_float(hi);
        g_W1lo[i] = __uint_as_float(lo);
    }
    if (i < 128 * 64) {
        split_tf32(W2[i], hi, lo);
        g_W2hi[i] = __uint_as_float(hi);
        g_W2lo[i] = __uint_as_float(lo);
    }
}

// ---------------------------------------------------------------- tensor GEMM
// C[rows rowbase..rowlim) = A @ W (raw). R7-proven tile: 128 rows x 64 cols,
// 8 warps, K in two 64-deep phases. W staged from PRE-SPLIT hi/lo globals
// via pure float4 copies (no per-block cvt); mainloop identical to R7.
template <int NCOLS>
__global__ void k_gemm_tc(const float* __restrict__ Aext,
                          int rowbase, int rowlim) {
    __shared__ float Whi[64][WSTRIDE];
    __shared__ float Wlo[64][WSTRIDE];

    const float* __restrict__ A = (NCOLS == 128) ? Aext : (const float*)g_t1;
    float* __restrict__ outp    = (NCOLS == 128) ? (float*)g_hs1 : (float*)g_hs2;
    const float* __restrict__ Whi_src = (NCOLS == 128) ? g_W1hi : g_W2hi;
    const float* __restrict__ Wlo_src = (NCOLS == 128) ? g_W1lo : g_W2lo;

    const int tid  = threadIdx.x;
    const int lane = tid & 31;
    const int wid  = tid >> 5;
    const int gID  = lane >> 2;
    const int tg   = lane & 3;
    const int col0 = blockIdx.y * 64;

    const int m0 = rowbase + blockIdx.x * 128 + wid * 16;
    const int r0 = m0 + gID;
    const int r1 = r0 + 8;
    const bool v0 = r0 < rowlim, v1 = r1 < rowlim;
    const float* A0 = A + (size_t)(v0 ? r0 : 0) * 128;
    const float* A1 = A + (size_t)(v1 ? r1 : 0) * 128;

    float acc[8][4];
#pragma unroll
    for (int i = 0; i < 8; i++)
#pragma unroll
        for (int j = 0; j < 4; j++) acc[i][j] = 0.f;

#pragma unroll
    for (int phase = 0; phase < 2; phase++) {
        const int kbase = phase * 64;
        if (phase) __syncthreads();

        // Stage 64 k-rows x 64 cols: vectorized copy of pre-split hi/lo.
#pragma unroll
        for (int idx = tid; idx < 64 * 16; idx += 256) {   // float4 units
            int nc4 = idx & 15;
            int k   = idx >> 4;
            long off = (long)(kbase + k) * NCOLS + col0 + nc4 * 4;
            *(float4*)&Whi[k][nc4 * 4] = *(const float4*)&Whi_src[off];
            *(float4*)&Wlo[k][nc4 * 4] = *(const float4*)&Wlo_src[off];
        }
        __syncthreads();

#pragma unroll
        for (int ks = 0; ks < 8; ks++) {
            const int k0 = ks * 8;
            float f0 = A0[kbase + k0 + tg];
            float f1 = A1[kbase + k0 + tg];
            float f2 = A0[kbase + k0 + tg + 4];
            float f3 = A1[kbase + k0 + tg + 4];
            unsigned ah0, al0, ah1, al1, ah2, al2, ah3, al3;
            split_tf32(f0, ah0, al0);
            split_tf32(f1, ah1, al1);
            split_tf32(f2, ah2, al2);
            split_tf32(f3, ah3, al3);

#pragma unroll
            for (int nf = 0; nf < 8; nf++) {
                const int nc = nf * 8 + gID;
                unsigned bh0 = __float_as_uint(Whi[k0 + tg][nc]);
                unsigned bh1 = __float_as_uint(Whi[k0 + tg + 4][nc]);
                unsigned bl0 = __float_as_uint(Wlo[k0 + tg][nc]);
                unsigned bl1 = __float_as_uint(Wlo[k0 + tg + 4][nc]);
                mma_tf32(acc[nf], ah0, ah1, ah2, ah3, bh0, bh1);  // hi*hi
                mma_tf32(acc[nf], ah0, ah1, ah2, ah3, bl0, bl1);  // hi*lo
                mma_tf32(acc[nf], al0, al1, al2, al3, bh0, bh1);  // lo*hi
            }
        }
    }

#pragma unroll
    for (int nf = 0; nf < 8; nf++) {
        int c = col0 + nf * 8 + 2 * tg;
        if (v0) *(float2*)&outp[(long)r0 * NCOLS + c] =
            make_float2(acc[nf][0], acc[nf][1]);
        if (v1) *(float2*)&outp[(long)r1 * NCOLS + c] =
            make_float2(acc[nf][2], acc[nf][3]);
    }
}

// ---------------------------------------------------------------- aggregation
// t1[d] = relu(dinv[d] * (sum_s dinv[s]*h[s] + dinv[d]*h[d]) + b1)
__global__ void k_agg1(const float* __restrict__ b1, int dbase, int dcnt) {
    int w    = (blockIdx.x * blockDim.x + threadIdx.x) >> 5;
    int lane = threadIdx.x & 31;
    if (w >= dcnt) return;
    const int d  = dbase + w;
    const int cc = min(g_cnt[d], CAP);
    const float4* hs = (const float4*)g_hs1;
    const long base = (long)d * CAP;

    float4 acc = make_float4(0.f, 0.f, 0.f, 0.f);
    int k0 = 0;
    for (; k0 + 32 <= cc; k0 += 32) {
        int   sl = g_bucket[base + k0 + lane];
        float dl = g_dinv[sl];
#pragma unroll
        for (int i = 0; i < 32; i++) {
            int   s = __shfl_sync(0xffffffffu, sl, i);
            float ws = __shfl_sync(0xffffffffu, dl, i);
            float4 v = hs[(long)s * 32 + lane];
            acc.x += ws * v.x; acc.y += ws * v.y;
            acc.z += ws * v.z; acc.w += ws * v.w;
        }
    }
    if (k0 < cc) {
        int   sl = (k0 + lane < cc) ? g_bucket[base + k0 + lane] : 0;
        float dl = g_dinv[sl];
        int rem = cc - k0;
        for (int i = 0; i < rem; i++) {
            int   s = __shfl_sync(0xffffffffu, sl, i);
            float ws = __shfl_sync(0xffffffffu, dl, i);
            float4 v = hs[(long)s * 32 + lane];
            acc.x += ws * v.x; acc.y += ws * v.y;
            acc.z += ws * v.z; acc.w += ws * v.w;
        }
    }
    float  di   = g_dinv[d];
    float4 self = hs[(long)d * 32 + lane];
    acc.x += di * self.x; acc.y += di * self.y;
    acc.z += di * self.z; acc.w += di * self.w;
    float4 bb = ((const float4*)b1)[lane];
    float4 o;
    o.x = fmaxf(di * acc.x + bb.x, 0.f);
    o.y = fmaxf(di * acc.y + bb.y, 0.f);
    o.z = fmaxf(di * acc.z + bb.z, 0.f);
    o.w = fmaxf(di * acc.w + bb.w, 0.f);
    ((float4*)g_t1)[(long)d * 32 + lane] = o;
}

__global__ void k_agg2(const float* __restrict__ b2, int n) {
    int gt   = blockIdx.x * blockDim.x + threadIdx.x;
    int grp  = gt >> 4;
    int j    = gt & 15;
    int lane = threadIdx.x & 31;
    unsigned gmask = 0xFFFFu << (lane & 16);
    if (grp >= n) return;
    const int d  = grp;
    const int cc = min(g_cnt[d], CAP);
    const float4* hs = (const float4*)g_hs2;
    const long base = (long)d * CAP;

    float4 acc = make_float4(0.f, 0.f, 0.f, 0.f);
    int k0 = 0;
    for (; k0 + 16 <= cc; k0 += 16) {
        int   sl = g_bucket[base + k0 + j];
        float dl = g_dinv[sl];
#pragma unroll
        for (int i = 0; i < 16; i++) {
            int   s = __shfl_sync(gmask, sl, i, 16);
            float ws = __shfl_sync(gmask, dl, i, 16);
            float4 v = hs[(long)s * 16 + j];
            acc.x += ws * v.x; acc.y += ws * v.y;
            acc.z += ws * v.z; acc.w += ws * v.w;
        }
    }
    if (k0 < cc) {
        int   sl = (k0 + j < cc) ? g_bucket[base + k0 + j] : 0;
        float dl = g_dinv[sl];
        int rem = cc - k0;
        for (int i = 0; i < rem; i++) {
            int   s = __shfl_sync(gmask, sl, i, 16);
            float ws = __shfl_sync(gmask, dl, i, 16);
            float4 v = hs[(long)s * 16 + j];
            acc.x += ws * v.x; acc.y += ws * v.y;
            acc.z += ws * v.z; acc.w += ws * v.w;
        }
    }
    float  di   = g_dinv[d];
    float4 self = hs[(long)d * 16 + j];
    acc.x += di * self.x; acc.y += di * self.y;
    acc.z += di * self.z; acc.w += di * self.w;
    float4 bb = ((const float4*)b2)[j];
    float4 o;
    o.x = di * acc.x + bb.x;
    o.y = di * acc.y + bb.y;
    o.z = di * acc.z + bb.z;
    o.w = di * acc.w + bb.w;
    ((float4*)g_z)[(long)d * 16 + j] = o;
}

// ---------------------------------------------------------------- decode
__global__ void k_decode(const unsigned* __restrict__ eli,
                         float* __restrict__ out, int EL, int n) {
    int gt = blockIdx.x * blockDim.x + threadIdx.x;
    int e  = gt >> 4;
    int j  = gt & 15;
    bool valid = (e < EL);
    int ec = valid ? e : (EL - 1);
    const int is64 = g_is64_eli;
    int u = edge_val(eli, ec, is64);
    int v = edge_val(eli, (long)EL + ec, is64);
    if ((unsigned)u >= (unsigned)n) u = 0;
    if ((unsigned)v >= (unsigned)n) v = 0;
    const float4* z4 = (const float4*)g_z;
    float4 a = z4[(long)u * 16 + j];
    float4 b = z4[(long)v * 16 + j];
    float p = a.x * b.x + a.y * b.y + a.z * b.z + a.w * b.w;
    p += __shfl_xor_sync(0xffffffffu, p, 8, 16);
    p += __shfl_xor_sync(0xffffffffu, p, 4, 16);
    p += __shfl_xor_sync(0xffffffffu, p, 2, 16);
    p += __shfl_xor_sync(0xffffffffu, p, 1, 16);
    if (valid && j == 0) out[e] = p;
}

// ---------------------------------------------------------------- launch
extern "C" void kernel_launch(void* const* d_in, const int* in_sizes, int n_in,
                              void* d_out, int out_size) {
    const float*    x   = (const float*)d_in[0];
    const unsigned* ei  = (const unsigned*)d_in[1];
    const unsigned* eli = (const unsigned*)d_in[2];
    const float*    W1  = (const float*)d_in[3];
    const float*    b1  = (const float*)d_in[4];
    const float*    W2  = (const float*)d_in[5];
    const float*    b2  = (const float*)d_in[6];
    float* out = (float*)d_out;

    const int n  = in_sizes[0] / 128;
    const int E  = in_sizes[1] / 2;
    const int EL = in_sizes[2] / 2;

    // Node chunks: A = [0, nA) multiple of 128, B = [nA, n).
    const int nA = ((n / 2) / 128) * 128;
    const int nB = n - nA;

    // Fork: side stream builds graph structure during splitW + gemm1.
    cudaEventRecord(g_evFork, 0);
    cudaStreamWaitEvent(g_s2, g_evFork, 0);

    k_init<<<(n + 255) / 256, 256, 0, g_s2>>>(ei, (long)in_sizes[1],
                                              eli, (long)in_sizes[2], n);
    k_build<<<(E / 2 + 255) / 256, 256, 0, g_s2>>>(ei, E, n);
    k_dinv<<<(n + 255) / 256, 256, 0, g_s2>>>(n);
    cudaEventRecord(g_evJoin, g_s2);

    // Main: pre-split weights, then gemm1.
    k_splitW<<<(128 * 128 + 255) / 256, 256>>>(W1, W2);
    dim3 g1((n + 127) / 128, 2);
    k_gemm_tc<128><<<g1, 256>>>(x, 0, n);
    cudaEventRecord(g_evG1, 0);

    // Main stream: needs graph (evJoin) before aggregation.
    cudaStreamWaitEvent(0, g_evJoin, 0);
    // Side stream: needs gemm1 (evG1) before its agg1 chunk.
    cudaStreamWaitEvent(g_s2, g_evG1, 0);

    // Pipelined chunks: agg1_A/gemm2_A on stream0 || agg1_B/gemm2_B on s2.
    k_agg1<<<(nA * 32 + 255) / 256, 256>>>(b1, 0, nA);
    k_agg1<<<(nB * 32 + 255) / 256, 256, 0, g_s2>>>(b1, nA, nB);

    dim3 g2a(nA / 128, 1);
    k_gemm_tc<64><<<g2a, 256>>>(nullptr, 0, nA);
    dim3 g2b((nB + 127) / 128, 1);
    k_gemm_tc<64><<<g2b, 256, 0, g_s2>>>(nullptr, nA, n);
    cudaEventRecord(g_evB, g_s2);
    cudaStreamWaitEvent(0, g_evB, 0);

    k_agg2<<<(n * 16 + 255) / 256, 256>>>(b2, n);

    k_decode<<<((long)EL * 16 + 255) / 256, 256>>>(eli, out, EL, n);
}